// round 15
// baseline (speedup 1.0000x reference)
#include <cuda_runtime.h>
#include <cuda_bf16.h>
#include <math.h>

#define EMB 128
#define NHEAD 8
#define DHEAD 16
#define KNBR 32
#define NMAX 2048

typedef unsigned long long u64;

// Scratch (no cudaMalloc allowed)
__device__ float4 g_cent[NMAX];
__device__ float  g_qkv [NMAX * 3 * EMB];
__device__ int    g_nbr [NMAX * KNBR];
__device__ float  g_o   [NMAX * EMB];

__device__ __forceinline__ float dot4(float4 a, float4 b) {
    return a.x*b.x + a.y*b.y + a.z*b.z + a.w*b.w;
}
__device__ __forceinline__ u64 ffma2(u64 a, u64 b, u64 c) {
    u64 d;
    asm("fma.rn.f32x2 %0, %1, %2, %3;" : "=l"(d) : "l"(a), "l"(b), "l"(c));
    return d;
}
__device__ __forceinline__ float f2sum(u64 v) {
    return __uint_as_float((unsigned)v) + __uint_as_float((unsigned)(v >> 32));
}

// ---------------------------------------------------------------------------
// Centroid kernel (stream B head): g_cent[i] from coords9. Tiny.
// ---------------------------------------------------------------------------
__global__ __launch_bounds__(256) void cent_kernel(
    const float* __restrict__ coords9, int n)
{
    int i = blockIdx.x * 256 + threadIdx.x;
    if (i >= n) return;
    const float inv3 = 1.0f / 3.0f;
    float cx = (coords9[i*9+0] + coords9[i*9+3] + coords9[i*9+6]) * inv3;
    float cy = (coords9[i*9+1] + coords9[i*9+4] + coords9[i*9+7]) * inv3;
    float cz = (coords9[i*9+2] + coords9[i*9+5] + coords9[i*9+8]) * inv3;
    g_cent[i] = make_float4(cx, cy, cz, 0.f);
}

// ---------------------------------------------------------------------------
// Selection kernel (stream B, overlaps qkv GEMM): exact top-32 per node via
// 256-bin 4-level radix (register keys, warp-aggregated gen histogram,
// tie-buffer fast path). Ties at rank-32 take lowest indices (matches jax);
// set order irrelevant. Writes g_nbr. ~1.3 KB smem -> high occupancy.
// ---------------------------------------------------------------------------
__global__ __launch_bounds__(256) void sel_kernel(int n)
{
    __shared__ unsigned s_hist[256];
    __shared__ int      s_tie[64];
    __shared__ unsigned s_Tkey, s_rem;
    __shared__ int      s_cnt, s_tcnt;

    int i    = blockIdx.x;
    int tid  = threadIdx.x;
    int lane = tid & 31;

    s_hist[tid] = 0u;
    if (tid == 0) { s_Tkey = 0u; s_rem = KNBR; s_cnt = 0; s_tcnt = 0; }
    __syncthreads();

    float4 c0 = g_cent[i];
    unsigned kreg[NMAX/256];
    #pragma unroll
    for (int u = 0; u < NMAX/256; u++) {
        int j = tid + u*256;
        unsigned k = 0xFFFFFFFFu;   // pad: bin 255, above all finite keys
        if (j < n) {
            float4 cj = g_cent[j];
            float dx = cj.x - c0.x, dy = cj.y - c0.y, dz = cj.z - c0.z;
            k = __float_as_uint(dx*dx + dy*dy + dz*dz);
        }
        kreg[u] = k;
        int b = k >> 24;
        unsigned grp = __match_any_sync(0xffffffffu, b);
        if ((grp & ((1u << lane) - 1u)) == 0u)
            atomicAdd(&s_hist[b], (unsigned)__popc(grp));
    }
    __syncthreads();

    #pragma unroll 1
    for (int level = 0; level < 4; level++) {
        int shift = 24 - level*8;

        if (tid < 32) {
            unsigned h[8]; unsigned lsum = 0u;
            #pragma unroll
            for (int u = 0; u < 8; u++) { h[u] = s_hist[lane*8 + u]; lsum += h[u]; }
            unsigned incl = lsum;
            #pragma unroll
            for (int off = 1; off < 32; off <<= 1) {
                unsigned v = __shfl_up_sync(0xffffffffu, incl, off);
                if (lane >= off) incl += v;
            }
            unsigned cum = incl - lsum;
            unsigned rem = s_rem;
            int bloc = -1; unsigned cb_loc = 0u;
            #pragma unroll
            for (int u = 0; u < 8; u++) {
                if (cum < rem && cum + h[u] >= rem) { bloc = lane*8 + u; cb_loc = cum; }
                cum += h[u];
            }
            unsigned bal = __ballot_sync(0xffffffffu, bloc >= 0);
            int src = __ffs(bal) - 1;
            if (lane == src) {
                s_Tkey |= ((unsigned)bloc) << shift;
                s_rem   = rem - cb_loc;
            }
        }
        __syncthreads();

        if (level < 3) {
            unsigned pref = s_Tkey >> shift;
            s_hist[tid] = 0u;
            __syncthreads();
            #pragma unroll
            for (int u = 0; u < NMAX/256; u++) {
                unsigned k = kreg[u];
                if ((k >> shift) == pref)
                    atomicAdd(&s_hist[(k >> (shift - 8)) & 0xFFu], 1u);
            }
            __syncthreads();
        }
    }

    unsigned T = s_Tkey;
    int need = (int)s_rem;
    int out_base = i * KNBR;
    #pragma unroll
    for (int u = 0; u < NMAX/256; u++) {
        unsigned k = kreg[u];
        if (k < T) {
            int p = atomicAdd(&s_cnt, 1);
            g_nbr[out_base + p] = tid + u*256;
        } else if (k == T) {
            int p = atomicAdd(&s_tcnt, 1);
            if (p < 64) s_tie[p] = tid + u*256;
        }
    }
    __syncthreads();

    if (tid < 32) {
        int base = s_cnt;
        int t = s_tcnt;
        if (t <= 64) {
            int v0 = (lane < t)      ? s_tie[lane]      : 0x7fffffff;
            int v1 = (lane + 32 < t) ? s_tie[lane + 32] : 0x7fffffff;
            #pragma unroll 1
            for (int it = 0; it < need; it++) {
                int mn = min(v0, v1);
                #pragma unroll
                for (int off = 16; off; off >>= 1)
                    mn = min(mn, __shfl_xor_sync(0xffffffffu, mn, off));
                if (v0 == mn) v0 = 0x7fffffff;
                else if (v1 == mn) v1 = 0x7fffffff;
                if (lane == 0) g_nbr[out_base + base + it] = mn;
            }
        } else {
            // degenerate fallback: ordered ballot scan, keys recomputed
            int need2 = need; int pos = base;
            #pragma unroll 1
            for (int u = 0; u < NMAX/32 && need2 > 0; u++) {
                int j = u*32 + lane;
                unsigned k = 0xFFFFFFFFu;
                if (j < n) {
                    float4 cj = g_cent[j];
                    float dx = cj.x - c0.x, dy = cj.y - c0.y, dz = cj.z - c0.z;
                    k = __float_as_uint(dx*dx + dy*dy + dz*dz);
                }
                unsigned beq = __ballot_sync(0xffffffffu, k == T);
                if (beq) {
                    int neq  = __popc(beq);
                    int take = need2 < neq ? need2 : neq;
                    if (k == T) {
                        int rank = __popc(beq & ((1u << lane) - 1u));
                        if (rank < take) g_nbr[out_base + pos + rank] = j;
                    }
                    pos  += take;
                    need2 -= take;
                }
            }
        }
    }
}

// ---------------------------------------------------------------------------
// QKV GEMM with fused input prep (proven R10): 32r x 96c, 4x3 f32x2 tile,
// 67KB smem -> 2 blocks/SM, grid (4,63)=252. No g_cent write (cent_kernel).
// ---------------------------------------------------------------------------
__global__ __launch_bounds__(256, 2) void qkv_gemm_kernel(
    const float* __restrict__ x, const float* __restrict__ coords9,
    const float* __restrict__ prompt,
    const float* __restrict__ pe_w, const float* __restrict__ pe_b,
    const float* __restrict__ pe_g, const float* __restrict__ pe_bt,
    const float* __restrict__ W, const float* __restrict__ bias, int n)
{
    extern __shared__ float smem[];
    float* As = smem;                 // 32*128
    float* Ws = smem + 32*128;        // 96*132 (padded rows)

    int row0 = blockIdx.y * 32;
    int col0 = blockIdx.x * 96;
    int tid  = threadIdx.x;
    int w    = tid >> 5;
    int lane = tid & 31;

    #pragma unroll
    for (int u = 0; u < 12; u++) {
        int lin = tid + u*256;
        int cc = lin >> 5, k4 = lin & 31;
        float4 wv = ((const float4*)(W + (size_t)(col0 + cc)*128))[k4];
        ((float4*)(Ws + cc*132))[k4] = wv;
    }

    #pragma unroll 1
    for (int u = 0; u < 4; u++) {
        int r = w*4 + u;
        int i = row0 + r;
        if (i >= n) {
            As[r*128 + lane] = 0.f; As[r*128 + 32 + lane] = 0.f;
            As[r*128 + 64 + lane] = 0.f; As[r*128 + 96 + lane] = 0.f;
            continue;
        }
        float cv = (lane < 9) ? coords9[i*9 + lane] : 0.f;
        const float inv3 = 1.0f / 3.0f;
        float cx = (__shfl_sync(0xffffffffu, cv, 0) + __shfl_sync(0xffffffffu, cv, 3) + __shfl_sync(0xffffffffu, cv, 6)) * inv3;
        float cy = (__shfl_sync(0xffffffffu, cv, 1) + __shfl_sync(0xffffffffu, cv, 4) + __shfl_sync(0xffffffffu, cv, 7)) * inv3;
        float cz = (__shfl_sync(0xffffffffu, cv, 2) + __shfl_sync(0xffffffffu, cv, 5) + __shfl_sync(0xffffffffu, cv, 8)) * inv3;

        float v = cx*pe_w[lane] + cy*pe_w[32+lane] + cz*pe_w[64+lane] + pe_b[lane];
        float h = 0.5f * v * (1.0f + erff(v * 0.70710678118654752f));

        float s = h, s2 = h*h;
        #pragma unroll
        for (int off = 16; off; off >>= 1) {
            s  += __shfl_xor_sync(0xffffffffu, s,  off);
            s2 += __shfl_xor_sync(0xffffffffu, s2, off);
        }
        float mu  = s * (1.0f/32.0f);
        float var = s2 * (1.0f/32.0f) - mu*mu;
        float inv = rsqrtf(var + 1e-5f);

        As[r*128 +      lane] = x[i*EMB +      lane] + prompt[     lane];
        As[r*128 + 32 + lane] = x[i*EMB + 32 + lane] + prompt[32 + lane];
        As[r*128 + 64 + lane] = x[i*EMB + 64 + lane] + prompt[64 + lane];
        As[r*128 + 96 + lane] = (h - mu) * inv * pe_g[lane] + pe_bt[lane];
    }
    __syncthreads();

    int tx = tid & 31;
    int ty = tid >> 5;
    const ulonglong2* wp[3];
    #pragma unroll
    for (int c = 0; c < 3; c++) wp[c] = (const ulonglong2*)(Ws + (tx + 32*c)*132);
    const ulonglong2* ap[4];
    #pragma unroll
    for (int r = 0; r < 4; r++) ap[r] = (const ulonglong2*)(As + (ty*4 + r)*128);

    u64 acc[4][3];
    #pragma unroll
    for (int r = 0; r < 4; r++)
        #pragma unroll
        for (int c = 0; c < 3; c++) acc[r][c] = 0ULL;

    #pragma unroll 4
    for (int k4 = 0; k4 < 32; k4++) {
        ulonglong2 wv[3], av[4];
        #pragma unroll
        for (int c = 0; c < 3; c++) wv[c] = wp[c][k4];
        #pragma unroll
        for (int r = 0; r < 4; r++) av[r] = ap[r][k4];
        #pragma unroll
        for (int r = 0; r < 4; r++)
            #pragma unroll
            for (int c = 0; c < 3; c++) {
                acc[r][c] = ffma2(av[r].x, wv[c].x, acc[r][c]);
                acc[r][c] = ffma2(av[r].y, wv[c].y, acc[r][c]);
            }
    }

    float bv[3];
    #pragma unroll
    for (int c = 0; c < 3; c++) bv[c] = bias[col0 + tx + 32*c];
    #pragma unroll
    for (int r = 0; r < 4; r++) {
        int gr = row0 + ty*4 + r;
        if (gr < n) {
            #pragma unroll
            for (int c = 0; c < 3; c++)
                g_qkv[(size_t)gr*384 + col0 + tx + 32*c] = f2sum(acc[r][c]) + bv[c];
        }
    }
}

// ---------------------------------------------------------------------------
// Attention only (proven R13): one block per node, head-per-warp, register V,
// deterministic partial reduce. Reads g_nbr.
// ---------------------------------------------------------------------------
__global__ __launch_bounds__(256) void attn_lite_kernel(int n)
{
    __shared__ float s_p[NHEAD][KNBR];       // 1 KB
    __shared__ float s_part[NHEAD][EMB];     // 4 KB

    int i    = blockIdx.x;
    int tid  = threadIdx.x;
    int w    = tid >> 5;
    int lane = tid & 31;

    int idx_l = g_nbr[i*KNBR + lane];
    int vrow[4];
    #pragma unroll
    for (int u = 0; u < 4; u++) vrow[u] = __shfl_sync(0xffffffffu, idx_l, w*4 + u);

    float4 vreg[4];
    #pragma unroll
    for (int u = 0; u < 4; u++)
        vreg[u] = ((const float4*)(g_qkv + (size_t)vrow[u]*384 + 256))[lane];

    {
        const float4* kp = (const float4*)(g_qkv + (size_t)idx_l*384 + 128 + w*DHEAD);
        const float4* qp = (const float4*)(g_qkv + (size_t)i*384 + w*DHEAD);
        float4 q0 = qp[0], q1 = qp[1], q2 = qp[2], q3 = qp[3];
        float4 k0 = kp[0], k1 = kp[1], k2 = kp[2], k3 = kp[3];
        float s = dot4(q0,k0) + dot4(q1,k1) + dot4(q2,k2) + dot4(q3,k3);
        s *= 0.25f;   // 1/sqrt(16)

        float m = s;
        #pragma unroll
        for (int off = 16; off; off >>= 1)
            m = fmaxf(m, __shfl_xor_sync(0xffffffffu, m, off));
        float p = expf(s - m);
        float den = p;
        #pragma unroll
        for (int off = 16; off; off >>= 1)
            den += __shfl_xor_sync(0xffffffffu, den, off);
        s_p[w][lane] = p / den;
    }
    __syncthreads();

    {
        int hh = lane >> 2;
        float4 acc = make_float4(0.f,0.f,0.f,0.f);
        #pragma unroll
        for (int u = 0; u < 4; u++) {
            float p = s_p[hh][w*4 + u];
            acc.x += p * vreg[u].x;
            acc.y += p * vreg[u].y;
            acc.z += p * vreg[u].z;
            acc.w += p * vreg[u].w;
        }
        ((float4*)s_part[w])[lane] = acc;
    }
    __syncthreads();

    if (tid < 128) {
        float o = 0.f;
        #pragma unroll
        for (int ww = 0; ww < NHEAD; ww++) o += s_part[ww][tid];
        g_o[(size_t)i*EMB + tid] = o;
    }
}

// ---------------------------------------------------------------------------
// Output GEMM (proven): 32 rows x 64 cols, 4x2 tile, float4. With sanitize.
// ---------------------------------------------------------------------------
__global__ __launch_bounds__(256) void out_gemm_kernel(
    const float* __restrict__ W, const float* __restrict__ bias,
    float* __restrict__ C, int n)
{
    extern __shared__ float smem[];
    float* As = smem;                 // 32*128
    float* Ws = smem + 32*128;        // 64*132

    int row0 = blockIdx.y * 32;
    int col0 = blockIdx.x * 64;
    int tid  = threadIdx.x;

    #pragma unroll
    for (int u = 0; u < 8; u++) {
        int lin = tid + u*256;
        int cc = lin >> 5, k4 = lin & 31;
        float4 wv = ((const float4*)(W + (size_t)(col0 + cc)*128))[k4];
        ((float4*)(Ws + cc*132))[k4] = wv;
    }
    #pragma unroll
    for (int u = 0; u < 4; u++) {
        int lin = tid + u*256;
        int r = lin >> 5, c4 = lin & 31;
        int gr = row0 + r;
        float4 av = make_float4(0.f,0.f,0.f,0.f);
        if (gr < n) av = ((const float4*)(g_o + (size_t)gr*128))[c4];
        ((float4*)(As + r*128))[c4] = av;
    }
    __syncthreads();

    int tx = tid & 31;
    int ty = tid >> 5;
    const float4* w0p = (const float4*)(Ws + tx*132);
    const float4* w1p = (const float4*)(Ws + (tx+32)*132);

    float acc[4][2] = {{0.f,0.f},{0.f,0.f},{0.f,0.f},{0.f,0.f}};
    #pragma unroll
    for (int k4 = 0; k4 < 32; k4++) {
        float4 w0 = w0p[k4], w1 = w1p[k4];
        #pragma unroll
        for (int r = 0; r < 4; r++) {
            float4 a = ((const float4*)(As + (ty*4+r)*128))[k4];
            acc[r][0] += dot4(a, w0);
            acc[r][1] += dot4(a, w1);
        }
    }

    int c0 = col0 + tx, c1 = col0 + tx + 32;
    float b0 = bias[c0], b1 = bias[c1];
    #pragma unroll
    for (int r = 0; r < 4; r++) {
        int gr = row0 + ty*4 + r;
        if (gr < n) {
            float v0 = acc[r][0] + b0;
            float v1 = acc[r][1] + b1;
            if (isnan(v0)) v0 = 0.f;
            if (isnan(v1)) v1 = 0.f;
            v0 = fminf(fmaxf(v0, -1e4f), 1e4f);
            v1 = fminf(fmaxf(v1, -1e4f), 1e4f);
            C[(size_t)gr*EMB + c0] = v0;
            C[(size_t)gr*EMB + c1] = v1;
        }
    }
}

// ---------------------------------------------------------------------------
// Launch: fork stream B (cent -> sel) concurrent with qkv on the main stream,
// join, then attn_lite -> out_gemm. All via event fork/join so the captured
// graph expresses the concurrency. Streams/events created per call (never
// destroyed mid-capture); no device memory is allocated.
// ---------------------------------------------------------------------------
extern "C" void kernel_launch(void* const* d_in, const int* in_sizes, int n_in,
                              void* d_out, int out_size)
{
    const float* x       = (const float*)d_in[0];
    const float* coords9 = (const float*)d_in[1];
    const float* prompt  = (const float*)d_in[2];
    const float* pe_w    = (const float*)d_in[3];
    const float* pe_b    = (const float*)d_in[4];
    const float* pe_g    = (const float*)d_in[5];
    const float* pe_bt   = (const float*)d_in[6];
    const float* in_w    = (const float*)d_in[7];
    const float* in_b    = (const float*)d_in[8];
    const float* out_w   = (const float*)d_in[9];
    const float* out_b   = (const float*)d_in[10];
    float* out = (float*)d_out;

    int n = in_sizes[0] / EMB;     // 2000
    int nrb = (n + 31) / 32;       // 63

    const int QKV_SMEM = (32*128 + 96*132) * (int)sizeof(float);    // 67072 B
    const int OUT_SMEM = (32*128 + 64*132) * (int)sizeof(float);    // 50176 B
    cudaFuncSetAttribute(qkv_gemm_kernel, cudaFuncAttributeMaxDynamicSharedMemorySize, QKV_SMEM);
    cudaFuncSetAttribute(out_gemm_kernel, cudaFuncAttributeMaxDynamicSharedMemorySize, OUT_SMEM);

    cudaStream_t sB;
    cudaEvent_t eFork, eJoin;
    cudaStreamCreateWithFlags(&sB, cudaStreamNonBlocking);
    cudaEventCreateWithFlags(&eFork, cudaEventDisableTiming);
    cudaEventCreateWithFlags(&eJoin, cudaEventDisableTiming);

    // fork: stream B depends on everything before this point
    cudaEventRecord(eFork, 0);
    cudaStreamWaitEvent(sB, eFork, 0);

    // stream B: centroids -> selection (independent of g_qkv)
    cent_kernel<<<(n + 255) / 256, 256, 0, sB>>>(coords9, n);
    sel_kernel<<<n, 256, 0, sB>>>(n);

    // main stream: QKV GEMM (runs concurrently with stream B)
    qkv_gemm_kernel<<<dim3(4, nrb), 256, QKV_SMEM>>>(
        x, coords9, prompt, pe_w, pe_b, pe_g, pe_bt, in_w, in_b, n);

    // join: main stream waits for selection
    cudaEventRecord(eJoin, sB);
    cudaStreamWaitEvent(0, eJoin, 0);

    attn_lite_kernel<<<n, 256>>>(n);
    out_gemm_kernel<<<dim3(2, nrb), 256, OUT_SMEM>>>(out_w, out_b, out, n);
}

// round 16
// speedup vs baseline: 1.0863x; 1.0863x over previous
#include <cuda_runtime.h>
#include <cuda_bf16.h>
#include <math.h>

#define EMB 128
#define NHEAD 8
#define DHEAD 16
#define KNBR 32
#define NMAX 2048

typedef unsigned long long u64;

// Scratch (no cudaMalloc allowed)
__device__ float4 g_cent[NMAX];
__device__ float  g_qkv [NMAX * 3 * EMB];
__device__ float  g_o   [NMAX * EMB];

__device__ __forceinline__ float dot4(float4 a, float4 b) {
    return a.x*b.x + a.y*b.y + a.z*b.z + a.w*b.w;
}
__device__ __forceinline__ u64 ffma2(u64 a, u64 b, u64 c) {
    u64 d;
    asm("fma.rn.f32x2 %0, %1, %2, %3;" : "=l"(d) : "l"(a), "l"(b), "l"(c));
    return d;
}
__device__ __forceinline__ float f2sum(u64 v) {
    return __uint_as_float((unsigned)v) + __uint_as_float((unsigned)(v >> 32));
}

// ---------------------------------------------------------------------------
// QKV GEMM with fused input prep (proven R10): 32r x 96c, 256 threads, 4x3
// f32x2 tile, 67KB smem -> 2 blocks/SM, grid (4,63)=252 -> single wave.
// Col-block 0 also writes g_cent.
// ---------------------------------------------------------------------------
__global__ __launch_bounds__(256, 2) void qkv_gemm_kernel(
    const float* __restrict__ x, const float* __restrict__ coords9,
    const float* __restrict__ prompt,
    const float* __restrict__ pe_w, const float* __restrict__ pe_b,
    const float* __restrict__ pe_g, const float* __restrict__ pe_bt,
    const float* __restrict__ W, const float* __restrict__ bias, int n)
{
    extern __shared__ float smem[];
    float* As = smem;                 // 32*128
    float* Ws = smem + 32*128;        // 96*132 (padded rows)

    int row0 = blockIdx.y * 32;
    int col0 = blockIdx.x * 96;
    int tid  = threadIdx.x;
    int w    = tid >> 5;
    int lane = tid & 31;

    #pragma unroll
    for (int u = 0; u < 12; u++) {
        int lin = tid + u*256;
        int cc = lin >> 5, k4 = lin & 31;
        float4 wv = ((const float4*)(W + (size_t)(col0 + cc)*128))[k4];
        ((float4*)(Ws + cc*132))[k4] = wv;
    }

    #pragma unroll 1
    for (int u = 0; u < 4; u++) {
        int r = w*4 + u;
        int i = row0 + r;
        if (i >= n) {
            As[r*128 + lane] = 0.f; As[r*128 + 32 + lane] = 0.f;
            As[r*128 + 64 + lane] = 0.f; As[r*128 + 96 + lane] = 0.f;
            continue;
        }
        float cv = (lane < 9) ? coords9[i*9 + lane] : 0.f;
        const float inv3 = 1.0f / 3.0f;
        float cx = (__shfl_sync(0xffffffffu, cv, 0) + __shfl_sync(0xffffffffu, cv, 3) + __shfl_sync(0xffffffffu, cv, 6)) * inv3;
        float cy = (__shfl_sync(0xffffffffu, cv, 1) + __shfl_sync(0xffffffffu, cv, 4) + __shfl_sync(0xffffffffu, cv, 7)) * inv3;
        float cz = (__shfl_sync(0xffffffffu, cv, 2) + __shfl_sync(0xffffffffu, cv, 5) + __shfl_sync(0xffffffffu, cv, 8)) * inv3;
        if (col0 == 0 && lane == 0) g_cent[i] = make_float4(cx, cy, cz, 0.f);

        float v = cx*pe_w[lane] + cy*pe_w[32+lane] + cz*pe_w[64+lane] + pe_b[lane];
        float h = 0.5f * v * (1.0f + erff(v * 0.70710678118654752f));

        float s = h, s2 = h*h;
        #pragma unroll
        for (int off = 16; off; off >>= 1) {
            s  += __shfl_xor_sync(0xffffffffu, s,  off);
            s2 += __shfl_xor_sync(0xffffffffu, s2, off);
        }
        float mu  = s * (1.0f/32.0f);
        float var = s2 * (1.0f/32.0f) - mu*mu;
        float inv = rsqrtf(var + 1e-5f);

        As[r*128 +      lane] = x[i*EMB +      lane] + prompt[     lane];
        As[r*128 + 32 + lane] = x[i*EMB + 32 + lane] + prompt[32 + lane];
        As[r*128 + 64 + lane] = x[i*EMB + 64 + lane] + prompt[64 + lane];
        As[r*128 + 96 + lane] = (h - mu) * inv * pe_g[lane] + pe_bt[lane];
    }
    __syncthreads();

    int tx = tid & 31;
    int ty = tid >> 5;
    const ulonglong2* wp[3];
    #pragma unroll
    for (int c = 0; c < 3; c++) wp[c] = (const ulonglong2*)(Ws + (tx + 32*c)*132);
    const ulonglong2* ap[4];
    #pragma unroll
    for (int r = 0; r < 4; r++) ap[r] = (const ulonglong2*)(As + (ty*4 + r)*128);

    u64 acc[4][3];
    #pragma unroll
    for (int r = 0; r < 4; r++)
        #pragma unroll
        for (int c = 0; c < 3; c++) acc[r][c] = 0ULL;

    #pragma unroll 4
    for (int k4 = 0; k4 < 32; k4++) {
        ulonglong2 wv[3], av[4];
        #pragma unroll
        for (int c = 0; c < 3; c++) wv[c] = wp[c][k4];
        #pragma unroll
        for (int r = 0; r < 4; r++) av[r] = ap[r][k4];
        #pragma unroll
        for (int r = 0; r < 4; r++)
            #pragma unroll
            for (int c = 0; c < 3; c++) {
                acc[r][c] = ffma2(av[r].x, wv[c].x, acc[r][c]);
                acc[r][c] = ffma2(av[r].y, wv[c].y, acc[r][c]);
            }
    }

    float bv[3];
    #pragma unroll
    for (int c = 0; c < 3; c++) bv[c] = bias[col0 + tx + 32*c];
    #pragma unroll
    for (int r = 0; r < 4; r++) {
        int gr = row0 + ty*4 + r;
        if (gr < n) {
            #pragma unroll
            for (int c = 0; c < 3; c++)
                g_qkv[(size_t)gr*384 + col0 + tx + 32*c] = f2sum(acc[r][c]) + bv[c];
        }
    }
}

// ---------------------------------------------------------------------------
// Fused top-K + sparse attention (R9 proven structure), occupancy-tuned:
// __launch_bounds__(256, 6) (regs <= 42 -> 6 blocks/SM), no s_key staging
// (fallback recomputes keys), __expf softmax. 256-bin 4-level radix with
// register keys, warp-aggregated gen histogram, tie-buffer fast path.
// Ties at rank-32 take lowest indices (matches jax); set order irrelevant.
// ---------------------------------------------------------------------------
__global__ __launch_bounds__(256, 6) void fused_attn_kernel(int n)
{
    __shared__ unsigned s_hist[256];          // 1 KB
    __shared__ float    s_p[NHEAD][KNBR];     // 1 KB
    __shared__ float    s_part[NHEAD][EMB];   // 4 KB
    __shared__ int      s_nbr[KNBR];
    __shared__ int      s_tie[64];
    __shared__ unsigned s_Tkey, s_rem;
    __shared__ int      s_cnt, s_tcnt;

    int i    = blockIdx.x;
    int tid  = threadIdx.x;
    int w    = tid >> 5;
    int lane = tid & 31;

    s_hist[tid] = 0u;
    if (tid == 0) { s_Tkey = 0u; s_rem = KNBR; s_cnt = 0; s_tcnt = 0; }
    __syncthreads();

    // ---- gen pass: keys (registers) + level-0 histogram, warp-aggregated ----
    float4 c0 = g_cent[i];
    unsigned kreg[NMAX/256];
    #pragma unroll
    for (int u = 0; u < NMAX/256; u++) {
        int j = tid + u*256;
        unsigned k = 0xFFFFFFFFu;   // pad: bin 255, above all finite keys
        if (j < n) {
            float4 cj = g_cent[j];
            float dx = cj.x - c0.x, dy = cj.y - c0.y, dz = cj.z - c0.z;
            k = __float_as_uint(dx*dx + dy*dy + dz*dz);
        }
        kreg[u] = k;
        int b = k >> 24;   // sign+exponent byte: few distinct values per warp
        unsigned grp = __match_any_sync(0xffffffffu, b);
        if ((grp & ((1u << lane) - 1u)) == 0u)      // group leader
            atomicAdd(&s_hist[b], (unsigned)__popc(grp));
    }
    __syncthreads();

    // ---- radix descent: 4 levels of 8 bits -------------------------------
    #pragma unroll 1
    for (int level = 0; level < 4; level++) {
        int shift = 24 - level*8;

        if (tid < 32) {   // warp 0 scans 256 bins (8 per lane)
            unsigned h[8]; unsigned lsum = 0u;
            #pragma unroll
            for (int u = 0; u < 8; u++) { h[u] = s_hist[lane*8 + u]; lsum += h[u]; }
            unsigned incl = lsum;
            #pragma unroll
            for (int off = 1; off < 32; off <<= 1) {
                unsigned v = __shfl_up_sync(0xffffffffu, incl, off);
                if (lane >= off) incl += v;
            }
            unsigned cum = incl - lsum;
            unsigned rem = s_rem;
            int bloc = -1; unsigned cb_loc = 0u;
            #pragma unroll
            for (int u = 0; u < 8; u++) {
                if (cum < rem && cum + h[u] >= rem) { bloc = lane*8 + u; cb_loc = cum; }
                cum += h[u];
            }
            unsigned bal = __ballot_sync(0xffffffffu, bloc >= 0);
            int src = __ffs(bal) - 1;
            if (lane == src) {
                s_Tkey |= ((unsigned)bloc) << shift;
                s_rem   = rem - cb_loc;
            }
        }
        __syncthreads();

        if (level < 3) {
            unsigned pref = s_Tkey >> shift;
            s_hist[tid] = 0u;
            __syncthreads();
            #pragma unroll
            for (int u = 0; u < NMAX/256; u++) {
                unsigned k = kreg[u];
                if ((k >> shift) == pref)
                    atomicAdd(&s_hist[(k >> (shift - 8)) & 0xFFu], 1u);
            }
            __syncthreads();
        }
    }

    // ---- emission: keys < T direct; keys == T into tie buffer ----
    unsigned T = s_Tkey;
    int need = (int)s_rem;
    #pragma unroll
    for (int u = 0; u < NMAX/256; u++) {
        unsigned k = kreg[u];
        if (k < T) {
            int p = atomicAdd(&s_cnt, 1);
            s_nbr[p] = tid + u*256;
        } else if (k == T) {
            int p = atomicAdd(&s_tcnt, 1);
            if (p < 64) s_tie[p] = tid + u*256;
        }
    }
    __syncthreads();

    if (tid < 32) {
        int base = s_cnt;
        int t = s_tcnt;
        if (t <= 64) {
            // select `need` smallest tie indices (typically t=need=1)
            int v0 = (lane < t)      ? s_tie[lane]      : 0x7fffffff;
            int v1 = (lane + 32 < t) ? s_tie[lane + 32] : 0x7fffffff;
            #pragma unroll 1
            for (int it = 0; it < need; it++) {
                int mn = min(v0, v1);
                #pragma unroll
                for (int off = 16; off; off >>= 1)
                    mn = min(mn, __shfl_xor_sync(0xffffffffu, mn, off));
                if (v0 == mn) v0 = 0x7fffffff;
                else if (v1 == mn) v1 = 0x7fffffff;
                if (lane == 0) s_nbr[base + it] = mn;
            }
        } else {
            // degenerate fallback: ordered ballot scan, keys recomputed
            int need2 = need; int pos = base;
            #pragma unroll 1
            for (int u = 0; u < NMAX/32 && need2 > 0; u++) {
                int j = u*32 + lane;
                unsigned k = 0xFFFFFFFFu;
                if (j < n) {
                    float4 cj = g_cent[j];
                    float dx = cj.x - c0.x, dy = cj.y - c0.y, dz = cj.z - c0.z;
                    k = __float_as_uint(dx*dx + dy*dy + dz*dz);
                }
                unsigned beq = __ballot_sync(0xffffffffu, k == T);
                if (beq) {
                    int neq  = __popc(beq);
                    int take = need2 < neq ? need2 : neq;
                    if (k == T) {
                        int rank = __popc(beq & ((1u << lane) - 1u));
                        if (rank < take) s_nbr[pos + rank] = j;
                    }
                    pos  += take;
                    need2 -= take;
                }
            }
        }
    }
    __syncthreads();

    // ---- attention (head-per-warp) ----
    int idx_l = s_nbr[lane];
    int vrow[4];
    #pragma unroll
    for (int u = 0; u < 4; u++) vrow[u] = s_nbr[w*4 + u];

    float4 vreg[4];
    #pragma unroll
    for (int u = 0; u < 4; u++)
        vreg[u] = ((const float4*)(g_qkv + (size_t)vrow[u]*384 + 256))[lane];

    {
        const float4* kp = (const float4*)(g_qkv + (size_t)idx_l*384 + 128 + w*DHEAD);
        const float4* qp = (const float4*)(g_qkv + (size_t)i*384 + w*DHEAD);
        float4 q0 = qp[0], q1 = qp[1], q2 = qp[2], q3 = qp[3];
        float4 k0 = kp[0], k1 = kp[1], k2 = kp[2], k3 = kp[3];
        float s = dot4(q0,k0) + dot4(q1,k1) + dot4(q2,k2) + dot4(q3,k3);
        s *= 0.25f;   // 1/sqrt(16)

        float m = s;
        #pragma unroll
        for (int off = 16; off; off >>= 1)
            m = fmaxf(m, __shfl_xor_sync(0xffffffffu, m, off));
        float p = __expf(s - m);
        float den = p;
        #pragma unroll
        for (int off = 16; off; off >>= 1)
            den += __shfl_xor_sync(0xffffffffu, den, off);
        s_p[w][lane] = p / den;
    }
    __syncthreads();

    {
        int hh = lane >> 2;
        float4 acc = make_float4(0.f,0.f,0.f,0.f);
        #pragma unroll
        for (int u = 0; u < 4; u++) {
            float p = s_p[hh][w*4 + u];
            acc.x += p * vreg[u].x;
            acc.y += p * vreg[u].y;
            acc.z += p * vreg[u].z;
            acc.w += p * vreg[u].w;
        }
        ((float4*)s_part[w])[lane] = acc;
    }
    __syncthreads();

    if (tid < 128) {
        float o = 0.f;
        #pragma unroll
        for (int ww = 0; ww < NHEAD; ww++) o += s_part[ww][tid];
        g_o[(size_t)i*EMB + tid] = o;
    }
}

// ---------------------------------------------------------------------------
// Output GEMM (proven): 32 rows x 64 cols, 256 threads, 4x2 tile, float4.
// Grid (2,63)=126 -> single wave. With sanitize.
// ---------------------------------------------------------------------------
__global__ __launch_bounds__(256) void out_gemm_kernel(
    const float* __restrict__ W, const float* __restrict__ bias,
    float* __restrict__ C, int n)
{
    extern __shared__ float smem[];
    float* As = smem;                 // 32*128
    float* Ws = smem + 32*128;        // 64*132

    int row0 = blockIdx.y * 32;
    int col0 = blockIdx.x * 64;
    int tid  = threadIdx.x;

    #pragma unroll
    for (int u = 0; u < 8; u++) {
        int lin = tid + u*256;
        int cc = lin >> 5, k4 = lin & 31;
        float4 wv = ((const float4*)(W + (size_t)(col0 + cc)*128))[k4];
        ((float4*)(Ws + cc*132))[k4] = wv;
    }
    #pragma unroll
    for (int u = 0; u < 4; u++) {
        int lin = tid + u*256;
        int r = lin >> 5, c4 = lin & 31;
        int gr = row0 + r;
        float4 av = make_float4(0.f,0.f,0.f,0.f);
        if (gr < n) av = ((const float4*)(g_o + (size_t)gr*128))[c4];
        ((float4*)(As + r*128))[c4] = av;
    }
    __syncthreads();

    int tx = tid & 31;
    int ty = tid >> 5;
    const float4* w0p = (const float4*)(Ws + tx*132);
    const float4* w1p = (const float4*)(Ws + (tx+32)*132);

    float acc[4][2] = {{0.f,0.f},{0.f,0.f},{0.f,0.f},{0.f,0.f}};
    #pragma unroll
    for (int k4 = 0; k4 < 32; k4++) {
        float4 w0 = w0p[k4], w1 = w1p[k4];
        #pragma unroll
        for (int r = 0; r < 4; r++) {
            float4 a = ((const float4*)(As + (ty*4+r)*128))[k4];
            acc[r][0] += dot4(a, w0);
            acc[r][1] += dot4(a, w1);
        }
    }

    int c0 = col0 + tx, c1 = col0 + tx + 32;
    float b0 = bias[c0], b1 = bias[c1];
    #pragma unroll
    for (int r = 0; r < 4; r++) {
        int gr = row0 + ty*4 + r;
        if (gr < n) {
            float v0 = acc[r][0] + b0;
            float v1 = acc[r][1] + b1;
            if (isnan(v0)) v0 = 0.f;
            if (isnan(v1)) v1 = 0.f;
            v0 = fminf(fmaxf(v0, -1e4f), 1e4f);
            v1 = fminf(fmaxf(v1, -1e4f), 1e4f);
            C[(size_t)gr*EMB + c0] = v0;
            C[(size_t)gr*EMB + c1] = v1;
        }
    }
}

// ---------------------------------------------------------------------------
extern "C" void kernel_launch(void* const* d_in, const int* in_sizes, int n_in,
                              void* d_out, int out_size)
{
    const float* x       = (const float*)d_in[0];
    const float* coords9 = (const float*)d_in[1];
    const float* prompt  = (const float*)d_in[2];
    const float* pe_w    = (const float*)d_in[3];
    const float* pe_b    = (const float*)d_in[4];
    const float* pe_g    = (const float*)d_in[5];
    const float* pe_bt   = (const float*)d_in[6];
    const float* in_w    = (const float*)d_in[7];
    const float* in_b    = (const float*)d_in[8];
    const float* out_w   = (const float*)d_in[9];
    const float* out_b   = (const float*)d_in[10];
    float* out = (float*)d_out;

    int n = in_sizes[0] / EMB;     // 2000
    int nrb = (n + 31) / 32;       // 63

    const int QKV_SMEM = (32*128 + 96*132) * (int)sizeof(float);    // 67072 B
    const int OUT_SMEM = (32*128 + 64*132) * (int)sizeof(float);    // 50176 B
    cudaFuncSetAttribute(qkv_gemm_kernel, cudaFuncAttributeMaxDynamicSharedMemorySize, QKV_SMEM);
    cudaFuncSetAttribute(out_gemm_kernel, cudaFuncAttributeMaxDynamicSharedMemorySize, OUT_SMEM);

    qkv_gemm_kernel<<<dim3(4, nrb), 256, QKV_SMEM>>>(
        x, coords9, prompt, pe_w, pe_b, pe_g, pe_bt, in_w, in_b, n);
    fused_attn_kernel<<<n, 256>>>(n);
    out_gemm_kernel<<<dim3(2, nrb), 256, OUT_SMEM>>>(out_w, out_b, out, n);
}

// round 17
// speedup vs baseline: 1.1099x; 1.0217x over previous
#include <cuda_runtime.h>
#include <cuda_bf16.h>
#include <math.h>

#define EMB 128
#define NHEAD 8
#define DHEAD 16
#define KNBR 32
#define NMAX 2048

typedef unsigned long long u64;

// Scratch (no cudaMalloc allowed)
__device__ float4 g_cent[NMAX];
__device__ float  g_qkv [NMAX * 3 * EMB];
__device__ float  g_o   [NMAX * EMB];

__device__ __forceinline__ float dot4(float4 a, float4 b) {
    return a.x*b.x + a.y*b.y + a.z*b.z + a.w*b.w;
}
__device__ __forceinline__ u64 ffma2(u64 a, u64 b, u64 c) {
    u64 d;
    asm("fma.rn.f32x2 %0, %1, %2, %3;" : "=l"(d) : "l"(a), "l"(b), "l"(c));
    return d;
}
__device__ __forceinline__ float f2sum(u64 v) {
    return __uint_as_float((unsigned)v) + __uint_as_float((unsigned)(v >> 32));
}

// ---------------------------------------------------------------------------
// QKV GEMM with fused input prep (proven R10): 32r x 96c, 256 threads, 4x3
// f32x2 tile, 67KB smem -> 2 blocks/SM, grid (4,63)=252 -> single wave.
// Col-block 0 also writes g_cent.
// ---------------------------------------------------------------------------
__global__ __launch_bounds__(256, 2) void qkv_gemm_kernel(
    const float* __restrict__ x, const float* __restrict__ coords9,
    const float* __restrict__ prompt,
    const float* __restrict__ pe_w, const float* __restrict__ pe_b,
    const float* __restrict__ pe_g, const float* __restrict__ pe_bt,
    const float* __restrict__ W, const float* __restrict__ bias, int n)
{
    extern __shared__ float smem[];
    float* As = smem;                 // 32*128
    float* Ws = smem + 32*128;        // 96*132 (padded rows)

    int row0 = blockIdx.y * 32;
    int col0 = blockIdx.x * 96;
    int tid  = threadIdx.x;
    int w    = tid >> 5;
    int lane = tid & 31;

    #pragma unroll
    for (int u = 0; u < 12; u++) {
        int lin = tid + u*256;
        int cc = lin >> 5, k4 = lin & 31;
        float4 wv = ((const float4*)(W + (size_t)(col0 + cc)*128))[k4];
        ((float4*)(Ws + cc*132))[k4] = wv;
    }

    #pragma unroll 1
    for (int u = 0; u < 4; u++) {
        int r = w*4 + u;
        int i = row0 + r;
        if (i >= n) {
            As[r*128 + lane] = 0.f; As[r*128 + 32 + lane] = 0.f;
            As[r*128 + 64 + lane] = 0.f; As[r*128 + 96 + lane] = 0.f;
            continue;
        }
        float cv = (lane < 9) ? coords9[i*9 + lane] : 0.f;
        const float inv3 = 1.0f / 3.0f;
        float cx = (__shfl_sync(0xffffffffu, cv, 0) + __shfl_sync(0xffffffffu, cv, 3) + __shfl_sync(0xffffffffu, cv, 6)) * inv3;
        float cy = (__shfl_sync(0xffffffffu, cv, 1) + __shfl_sync(0xffffffffu, cv, 4) + __shfl_sync(0xffffffffu, cv, 7)) * inv3;
        float cz = (__shfl_sync(0xffffffffu, cv, 2) + __shfl_sync(0xffffffffu, cv, 5) + __shfl_sync(0xffffffffu, cv, 8)) * inv3;
        if (col0 == 0 && lane == 0) g_cent[i] = make_float4(cx, cy, cz, 0.f);

        float v = cx*pe_w[lane] + cy*pe_w[32+lane] + cz*pe_w[64+lane] + pe_b[lane];
        float h = 0.5f * v * (1.0f + erff(v * 0.70710678118654752f));

        float s = h, s2 = h*h;
        #pragma unroll
        for (int off = 16; off; off >>= 1) {
            s  += __shfl_xor_sync(0xffffffffu, s,  off);
            s2 += __shfl_xor_sync(0xffffffffu, s2, off);
        }
        float mu  = s * (1.0f/32.0f);
        float var = s2 * (1.0f/32.0f) - mu*mu;
        float inv = rsqrtf(var + 1e-5f);

        As[r*128 +      lane] = x[i*EMB +      lane] + prompt[     lane];
        As[r*128 + 32 + lane] = x[i*EMB + 32 + lane] + prompt[32 + lane];
        As[r*128 + 64 + lane] = x[i*EMB + 64 + lane] + prompt[64 + lane];
        As[r*128 + 96 + lane] = (h - mu) * inv * pe_g[lane] + pe_bt[lane];
    }
    __syncthreads();

    int tx = tid & 31;
    int ty = tid >> 5;
    const ulonglong2* wp[3];
    #pragma unroll
    for (int c = 0; c < 3; c++) wp[c] = (const ulonglong2*)(Ws + (tx + 32*c)*132);
    const ulonglong2* ap[4];
    #pragma unroll
    for (int r = 0; r < 4; r++) ap[r] = (const ulonglong2*)(As + (ty*4 + r)*128);

    u64 acc[4][3];
    #pragma unroll
    for (int r = 0; r < 4; r++)
        #pragma unroll
        for (int c = 0; c < 3; c++) acc[r][c] = 0ULL;

    #pragma unroll 4
    for (int k4 = 0; k4 < 32; k4++) {
        ulonglong2 wv[3], av[4];
        #pragma unroll
        for (int c = 0; c < 3; c++) wv[c] = wp[c][k4];
        #pragma unroll
        for (int r = 0; r < 4; r++) av[r] = ap[r][k4];
        #pragma unroll
        for (int r = 0; r < 4; r++)
            #pragma unroll
            for (int c = 0; c < 3; c++) {
                acc[r][c] = ffma2(av[r].x, wv[c].x, acc[r][c]);
                acc[r][c] = ffma2(av[r].y, wv[c].y, acc[r][c]);
            }
    }

    float bv[3];
    #pragma unroll
    for (int c = 0; c < 3; c++) bv[c] = bias[col0 + tx + 32*c];
    #pragma unroll
    for (int r = 0; r < 4; r++) {
        int gr = row0 + ty*4 + r;
        if (gr < n) {
            #pragma unroll
            for (int c = 0; c < 3; c++)
                g_qkv[(size_t)gr*384 + col0 + tx + 32*c] = f2sum(acc[r][c]) + bv[c];
        }
    }
}

// ---------------------------------------------------------------------------
// Fused top-K + sparse attention (proven R16). PDL: histogram/counter init
// runs before cudaGridDependencySynchronize(); g_cent reads after.
// ---------------------------------------------------------------------------
__global__ __launch_bounds__(256, 6) void fused_attn_kernel(int n)
{
    __shared__ unsigned s_hist[256];          // 1 KB
    __shared__ float    s_p[NHEAD][KNBR];     // 1 KB
    __shared__ float    s_part[NHEAD][EMB];   // 4 KB
    __shared__ int      s_nbr[KNBR];
    __shared__ int      s_tie[64];
    __shared__ unsigned s_Tkey, s_rem;
    __shared__ int      s_cnt, s_tcnt;

    int i    = blockIdx.x;
    int tid  = threadIdx.x;
    int w    = tid >> 5;
    int lane = tid & 31;

    // dependency-free preamble
    s_hist[tid] = 0u;
    if (tid == 0) { s_Tkey = 0u; s_rem = KNBR; s_cnt = 0; s_tcnt = 0; }
    __syncthreads();

    // wait for qkv grid (g_cent / g_qkv)
    cudaGridDependencySynchronize();

    // ---- gen pass: keys (registers) + level-0 histogram, warp-aggregated ----
    float4 c0 = g_cent[i];
    unsigned kreg[NMAX/256];
    #pragma unroll
    for (int u = 0; u < NMAX/256; u++) {
        int j = tid + u*256;
        unsigned k = 0xFFFFFFFFu;   // pad: bin 255, above all finite keys
        if (j < n) {
            float4 cj = g_cent[j];
            float dx = cj.x - c0.x, dy = cj.y - c0.y, dz = cj.z - c0.z;
            k = __float_as_uint(dx*dx + dy*dy + dz*dz);
        }
        kreg[u] = k;
        int b = k >> 24;   // sign+exponent byte: few distinct values per warp
        unsigned grp = __match_any_sync(0xffffffffu, b);
        if ((grp & ((1u << lane) - 1u)) == 0u)      // group leader
            atomicAdd(&s_hist[b], (unsigned)__popc(grp));
    }
    __syncthreads();

    // ---- radix descent: 4 levels of 8 bits -------------------------------
    #pragma unroll 1
    for (int level = 0; level < 4; level++) {
        int shift = 24 - level*8;

        if (tid < 32) {   // warp 0 scans 256 bins (8 per lane)
            unsigned h[8]; unsigned lsum = 0u;
            #pragma unroll
            for (int u = 0; u < 8; u++) { h[u] = s_hist[lane*8 + u]; lsum += h[u]; }
            unsigned incl = lsum;
            #pragma unroll
            for (int off = 1; off < 32; off <<= 1) {
                unsigned v = __shfl_up_sync(0xffffffffu, incl, off);
                if (lane >= off) incl += v;
            }
            unsigned cum = incl - lsum;
            unsigned rem = s_rem;
            int bloc = -1; unsigned cb_loc = 0u;
            #pragma unroll
            for (int u = 0; u < 8; u++) {
                if (cum < rem && cum + h[u] >= rem) { bloc = lane*8 + u; cb_loc = cum; }
                cum += h[u];
            }
            unsigned bal = __ballot_sync(0xffffffffu, bloc >= 0);
            int src = __ffs(bal) - 1;
            if (lane == src) {
                s_Tkey |= ((unsigned)bloc) << shift;
                s_rem   = rem - cb_loc;
            }
        }
        __syncthreads();

        if (level < 3) {
            unsigned pref = s_Tkey >> shift;
            s_hist[tid] = 0u;
            __syncthreads();
            #pragma unroll
            for (int u = 0; u < NMAX/256; u++) {
                unsigned k = kreg[u];
                if ((k >> shift) == pref)
                    atomicAdd(&s_hist[(k >> (shift - 8)) & 0xFFu], 1u);
            }
            __syncthreads();
        }
    }

    // ---- emission: keys < T direct; keys == T into tie buffer ----
    unsigned T = s_Tkey;
    int need = (int)s_rem;
    #pragma unroll
    for (int u = 0; u < NMAX/256; u++) {
        unsigned k = kreg[u];
        if (k < T) {
            int p = atomicAdd(&s_cnt, 1);
            s_nbr[p] = tid + u*256;
        } else if (k == T) {
            int p = atomicAdd(&s_tcnt, 1);
            if (p < 64) s_tie[p] = tid + u*256;
        }
    }
    __syncthreads();

    if (tid < 32) {
        int base = s_cnt;
        int t = s_tcnt;
        if (t <= 64) {
            // select `need` smallest tie indices (typically t=need=1)
            int v0 = (lane < t)      ? s_tie[lane]      : 0x7fffffff;
            int v1 = (lane + 32 < t) ? s_tie[lane + 32] : 0x7fffffff;
            #pragma unroll 1
            for (int it = 0; it < need; it++) {
                int mn = min(v0, v1);
                #pragma unroll
                for (int off = 16; off; off >>= 1)
                    mn = min(mn, __shfl_xor_sync(0xffffffffu, mn, off));
                if (v0 == mn) v0 = 0x7fffffff;
                else if (v1 == mn) v1 = 0x7fffffff;
                if (lane == 0) s_nbr[base + it] = mn;
            }
        } else {
            // degenerate fallback: ordered ballot scan, keys recomputed
            int need2 = need; int pos = base;
            #pragma unroll 1
            for (int u = 0; u < NMAX/32 && need2 > 0; u++) {
                int j = u*32 + lane;
                unsigned k = 0xFFFFFFFFu;
                if (j < n) {
                    float4 cj = g_cent[j];
                    float dx = cj.x - c0.x, dy = cj.y - c0.y, dz = cj.z - c0.z;
                    k = __float_as_uint(dx*dx + dy*dy + dz*dz);
                }
                unsigned beq = __ballot_sync(0xffffffffu, k == T);
                if (beq) {
                    int neq  = __popc(beq);
                    int take = need2 < neq ? need2 : neq;
                    if (k == T) {
                        int rank = __popc(beq & ((1u << lane) - 1u));
                        if (rank < take) s_nbr[pos + rank] = j;
                    }
                    pos  += take;
                    need2 -= take;
                }
            }
        }
    }
    __syncthreads();

    // ---- attention (head-per-warp) ----
    int idx_l = s_nbr[lane];
    int vrow[4];
    #pragma unroll
    for (int u = 0; u < 4; u++) vrow[u] = s_nbr[w*4 + u];

    float4 vreg[4];
    #pragma unroll
    for (int u = 0; u < 4; u++)
        vreg[u] = ((const float4*)(g_qkv + (size_t)vrow[u]*384 + 256))[lane];

    {
        const float4* kp = (const float4*)(g_qkv + (size_t)idx_l*384 + 128 + w*DHEAD);
        const float4* qp = (const float4*)(g_qkv + (size_t)i*384 + w*DHEAD);
        float4 q0 = qp[0], q1 = qp[1], q2 = qp[2], q3 = qp[3];
        float4 k0 = kp[0], k1 = kp[1], k2 = kp[2], k3 = kp[3];
        float s = dot4(q0,k0) + dot4(q1,k1) + dot4(q2,k2) + dot4(q3,k3);
        s *= 0.25f;   // 1/sqrt(16)

        float m = s;
        #pragma unroll
        for (int off = 16; off; off >>= 1)
            m = fmaxf(m, __shfl_xor_sync(0xffffffffu, m, off));
        float p = __expf(s - m);
        float den = p;
        #pragma unroll
        for (int off = 16; off; off >>= 1)
            den += __shfl_xor_sync(0xffffffffu, den, off);
        s_p[w][lane] = p / den;
    }
    __syncthreads();

    {
        int hh = lane >> 2;
        float4 acc = make_float4(0.f,0.f,0.f,0.f);
        #pragma unroll
        for (int u = 0; u < 4; u++) {
            float p = s_p[hh][w*4 + u];
            acc.x += p * vreg[u].x;
            acc.y += p * vreg[u].y;
            acc.z += p * vreg[u].z;
            acc.w += p * vreg[u].w;
        }
        ((float4*)s_part[w])[lane] = acc;
    }
    __syncthreads();

    if (tid < 128) {
        float o = 0.f;
        #pragma unroll
        for (int ww = 0; ww < NHEAD; ww++) o += s_part[ww][tid];
        g_o[(size_t)i*EMB + tid] = o;
    }
}

// ---------------------------------------------------------------------------
// Output GEMM (proven). PDL: the full 33KB W-tile smem staging runs BEFORE
// cudaGridDependencySynchronize(); only the g_o-dependent As load is after.
// ---------------------------------------------------------------------------
__global__ __launch_bounds__(256) void out_gemm_kernel(
    const float* __restrict__ W, const float* __restrict__ bias,
    float* __restrict__ C, int n)
{
    extern __shared__ float smem[];
    float* As = smem;                 // 32*128
    float* Ws = smem + 32*128;        // 64*132

    int row0 = blockIdx.y * 32;
    int col0 = blockIdx.x * 64;
    int tid  = threadIdx.x;

    // dependency-free preamble: W tile (weights are kernel inputs)
    #pragma unroll
    for (int u = 0; u < 8; u++) {
        int lin = tid + u*256;
        int cc = lin >> 5, k4 = lin & 31;
        float4 wv = ((const float4*)(W + (size_t)(col0 + cc)*128))[k4];
        ((float4*)(Ws + cc*132))[k4] = wv;
    }

    // wait for attn grid (g_o)
    cudaGridDependencySynchronize();

    #pragma unroll
    for (int u = 0; u < 4; u++) {
        int lin = tid + u*256;
        int r = lin >> 5, c4 = lin & 31;
        int gr = row0 + r;
        float4 av = make_float4(0.f,0.f,0.f,0.f);
        if (gr < n) av = ((const float4*)(g_o + (size_t)gr*128))[c4];
        ((float4*)(As + r*128))[c4] = av;
    }
    __syncthreads();

    int tx = tid & 31;
    int ty = tid >> 5;
    const float4* w0p = (const float4*)(Ws + tx*132);
    const float4* w1p = (const float4*)(Ws + (tx+32)*132);

    float acc[4][2] = {{0.f,0.f},{0.f,0.f},{0.f,0.f},{0.f,0.f}};
    #pragma unroll
    for (int k4 = 0; k4 < 32; k4++) {
        float4 w0 = w0p[k4], w1 = w1p[k4];
        #pragma unroll
        for (int r = 0; r < 4; r++) {
            float4 a = ((const float4*)(As + (ty*4+r)*128))[k4];
            acc[r][0] += dot4(a, w0);
            acc[r][1] += dot4(a, w1);
        }
    }

    int c0 = col0 + tx, c1 = col0 + tx + 32;
    float b0 = bias[c0], b1 = bias[c1];
    #pragma unroll
    for (int r = 0; r < 4; r++) {
        int gr = row0 + ty*4 + r;
        if (gr < n) {
            float v0 = acc[r][0] + b0;
            float v1 = acc[r][1] + b1;
            if (isnan(v0)) v0 = 0.f;
            if (isnan(v1)) v1 = 0.f;
            v0 = fminf(fmaxf(v0, -1e4f), 1e4f);
            v1 = fminf(fmaxf(v1, -1e4f), 1e4f);
            C[(size_t)gr*EMB + c0] = v0;
            C[(size_t)gr*EMB + c1] = v1;
        }
    }
}

// ---------------------------------------------------------------------------
// Launch: qkv normally; attn and out via cudaLaunchKernelEx with the
// programmatic-stream-serialization (PDL) attribute so their blocks can
// dispatch while the predecessor's tail drains. Graph-capturable (CUDA 12+
// encodes programmatic edges in captured graphs). No allocations.
// ---------------------------------------------------------------------------
extern "C" void kernel_launch(void* const* d_in, const int* in_sizes, int n_in,
                              void* d_out, int out_size)
{
    const float* x       = (const float*)d_in[0];
    const float* coords9 = (const float*)d_in[1];
    const float* prompt  = (const float*)d_in[2];
    const float* pe_w    = (const float*)d_in[3];
    const float* pe_b    = (const float*)d_in[4];
    const float* pe_g    = (const float*)d_in[5];
    const float* pe_bt   = (const float*)d_in[6];
    const float* in_w    = (const float*)d_in[7];
    const float* in_b    = (const float*)d_in[8];
    const float* out_w   = (const float*)d_in[9];
    const float* out_b   = (const float*)d_in[10];
    float* out = (float*)d_out;

    int n = in_sizes[0] / EMB;     // 2000
    int nrb = (n + 31) / 32;       // 63

    const int QKV_SMEM = (32*128 + 96*132) * (int)sizeof(float);    // 67072 B
    const int OUT_SMEM = (32*128 + 64*132) * (int)sizeof(float);    // 50176 B
    cudaFuncSetAttribute(qkv_gemm_kernel, cudaFuncAttributeMaxDynamicSharedMemorySize, QKV_SMEM);
    cudaFuncSetAttribute(out_gemm_kernel, cudaFuncAttributeMaxDynamicSharedMemorySize, OUT_SMEM);

    qkv_gemm_kernel<<<dim3(4, nrb), 256, QKV_SMEM>>>(
        x, coords9, prompt, pe_w, pe_b, pe_g, pe_bt, in_w, in_b, n);

    cudaLaunchAttribute pdl[1];
    pdl[0].id = cudaLaunchAttributeProgrammaticStreamSerialization;
    pdl[0].val.programmaticStreamSerializationAllowed = 1;

    {
        cudaLaunchConfig_t cfg = {};
        cfg.gridDim  = dim3((unsigned)n, 1, 1);
        cfg.blockDim = dim3(256, 1, 1);
        cfg.dynamicSmemBytes = 0;
        cfg.stream = 0;
        cfg.attrs = pdl;
        cfg.numAttrs = 1;
        cudaLaunchKernelEx(&cfg, fused_attn_kernel, n);
    }
    {
        cudaLaunchConfig_t cfg = {};
        cfg.gridDim  = dim3(2, (unsigned)nrb, 1);
        cfg.blockDim = dim3(256, 1, 1);
        cfg.dynamicSmemBytes = OUT_SMEM;
        cfg.stream = 0;
        cfg.attrs = pdl;
        cfg.numAttrs = 1;
        cudaLaunchKernelEx(&cfg, out_gemm_kernel, out_w, out_b, out, n);
    }
}